// round 2
// baseline (speedup 1.0000x reference)
#include <cuda_runtime.h>
#include <cuda_bf16.h>

// ---------------------------------------------------------------------------
// ConvVAE2d: patchify -> GEMM+ReLU -> GEMM -> (slice mu) -> GEMM+ReLU ->
//            GEMM+sigmoid -> unpatchify ; plus transposed mu_logvar output.
//
// Shapes: B=256, C=3, H=W=128, K=16 -> tokens T = 16384, P = 768,
//         HID = 2048, L = 256 (2L = 512).
// ---------------------------------------------------------------------------

#define T_TOKENS 16384
#define P_DIM    768
#define HID_DIM  2048
#define L2_DIM   512     // 2*L
#define L_DIM    256

// Scratch (device globals: allocation-free per harness rules)
__device__ float g_patches[T_TOKENS * P_DIM];    // 48 MiB
__device__ float g_he[T_TOKENS * HID_DIM];       // 128 MiB
__device__ float g_ml[T_TOKENS * L2_DIM];        // 32 MiB
__device__ float g_hd[T_TOKENS * HID_DIM];       // 128 MiB
__device__ float g_dec[T_TOKENS * P_DIM];        // 48 MiB

// ---------------------------------------------------------------------------
// Tiled SGEMM: C[M,N] = act(A[M,K] @ B[K,N] + bias[N])
// BM=BN=64, BK=16, 256 threads, 4x4 microtile per thread.
// All dims are multiples of the tile sizes for this problem (no guards).
// EPI: 0 = none, 1 = relu, 2 = sigmoid
// ---------------------------------------------------------------------------
template<int EPI>
__global__ __launch_bounds__(256) void sgemm_kernel(
    const float* __restrict__ A, int lda,
    const float* __restrict__ B, int ldb,
    const float* __restrict__ bias,
    float* __restrict__ C, int ldc,
    int Kd)
{
    constexpr int BM = 64, BN = 64, BK = 16;

    __shared__ float As[BK][BM];   // A tile, transposed (k-major)
    __shared__ float Bs[BK][BN];

    const int tid = threadIdx.x;
    const int tx  = tid & 15;   // 0..15 -> col group
    const int ty  = tid >> 4;   // 0..15 -> row group

    const int block_row = blockIdx.y * BM;
    const int block_col = blockIdx.x * BN;

    // A-tile load map: thread loads float4; covers 64 rows x 16 cols
    const int a_row = tid >> 2;          // 0..63
    const int a_col = (tid & 3) * 4;     // 0,4,8,12
    // B-tile load map: covers 16 rows x 64 cols
    const int b_row = tid >> 4;          // 0..15
    const int b_col = (tid & 15) * 4;    // 0..60

    const float* Aptr = A + (long)(block_row + a_row) * lda + a_col;
    const float* Bptr = B + (long)b_row * ldb + block_col + b_col;

    float acc[4][4] = {};

    for (int k0 = 0; k0 < Kd; k0 += BK) {
        const float4 av = *reinterpret_cast<const float4*>(Aptr);
        const float4 bv = *reinterpret_cast<const float4*>(Bptr);
        As[a_col + 0][a_row] = av.x;
        As[a_col + 1][a_row] = av.y;
        As[a_col + 2][a_row] = av.z;
        As[a_col + 3][a_row] = av.w;
        *reinterpret_cast<float4*>(&Bs[b_row][b_col]) = bv;
        __syncthreads();

        #pragma unroll
        for (int k = 0; k < BK; k++) {
            const float4 ra = *reinterpret_cast<const float4*>(&As[k][ty * 4]);
            const float4 rb = *reinterpret_cast<const float4*>(&Bs[k][tx * 4]);
            const float ar[4] = {ra.x, ra.y, ra.z, ra.w};
            const float br[4] = {rb.x, rb.y, rb.z, rb.w};
            #pragma unroll
            for (int i = 0; i < 4; i++)
                #pragma unroll
                for (int j = 0; j < 4; j++)
                    acc[i][j] = fmaf(ar[i], br[j], acc[i][j]);
        }
        __syncthreads();

        Aptr += BK;
        Bptr += (long)BK * ldb;
    }

    #pragma unroll
    for (int i = 0; i < 4; i++) {
        const int row = block_row + ty * 4 + i;
        #pragma unroll
        for (int j = 0; j < 4; j++) {
            const int col = block_col + tx * 4 + j;
            float v = acc[i][j] + bias[col];
            if (EPI == 1)      v = fmaxf(v, 0.0f);
            else if (EPI == 2) v = 1.0f / (1.0f + expf(-v));
            C[(long)row * ldc + col] = v;
        }
    }
}

// ---------------------------------------------------------------------------
// patches[token, c*256 + kh*16 + kw] = x[b, c, gh*16+kh, gw*16+kw]
// token = ((b*8)+gh)*8 + gw.  Iterate linearly over patches -> both sides
// have kw fastest -> coalesced.
// ---------------------------------------------------------------------------
__global__ void patchify_kernel(const float* __restrict__ x,
                                float* __restrict__ p, int n)
{
    int i = blockIdx.x * blockDim.x + threadIdx.x;
    if (i >= n) return;
    const int kw    = i & 15;
    const int kh    = (i >> 4) & 15;
    const int c     = (i >> 8) % 3;
    const int token = i / P_DIM;
    const int gw = token & 7;
    const int gh = (token >> 3) & 7;
    const int b  = token >> 6;
    const long src = ((long)(b * 3 + c) * 128 + gh * 16 + kh) * 128 + gw * 16 + kw;
    p[i] = x[src];
}

// recon[b, c, h, w] = dec[token, c*256 + kh*16 + kw]
__global__ void unpatchify_kernel(const float* __restrict__ dec,
                                  float* __restrict__ recon, int n)
{
    int i = blockIdx.x * blockDim.x + threadIdx.x;
    if (i >= n) return;
    const int w = i & 127;
    const int h = (i >> 7) & 127;
    const int c = (i >> 14) % 3;
    const int b = i / (3 * 128 * 128);
    const int gh = h >> 4, kh = h & 15;
    const int gw = w >> 4, kw = w & 15;
    const int token = ((b * 8) + gh) * 8 + gw;
    recon[i] = dec[(long)token * P_DIM + c * 256 + kh * 16 + kw];
}

// out2[b, l, g] = ml[b*64+g, l]   (g = gh*8+gw in 0..63, l in 0..511)
__global__ void transpose_ml_kernel(const float* __restrict__ ml,
                                    float* __restrict__ out2, int n)
{
    int i = blockIdx.x * blockDim.x + threadIdx.x;
    if (i >= n) return;
    const int g = i & 63;
    const int l = (i >> 6) & 511;
    const int b = i >> 15;
    out2[i] = ml[(long)(b * 64 + g) * L2_DIM + l];
}

// ---------------------------------------------------------------------------
extern "C" void kernel_launch(void* const* d_in, const int* in_sizes, int n_in,
                              void* d_out, int out_size)
{
    const float* x      = (const float*)d_in[0];
    const float* w_enc1 = (const float*)d_in[1];
    const float* b_enc1 = (const float*)d_in[2];
    const float* w_enc2 = (const float*)d_in[3];
    const float* b_enc2 = (const float*)d_in[4];
    const float* w_dec1 = (const float*)d_in[5];
    const float* b_dec1 = (const float*)d_in[6];
    const float* w_dec2 = (const float*)d_in[7];
    const float* b_dec2 = (const float*)d_in[8];

    float* patches; float* he; float* ml; float* hd; float* dec;
    cudaGetSymbolAddress((void**)&patches, g_patches);
    cudaGetSymbolAddress((void**)&he,      g_he);
    cudaGetSymbolAddress((void**)&ml,      g_ml);
    cudaGetSymbolAddress((void**)&hd,      g_hd);
    cudaGetSymbolAddress((void**)&dec,     g_dec);

    float* out   = (float*)d_out;
    float* recon = out;                                  // 256*3*128*128
    float* ml2d  = out + (long)256 * 3 * 128 * 128;      // 256*512*64

    const int n_img = 256 * 3 * 128 * 128;   // 12,582,912
    const int n_ml2 = 256 * 512 * 64;        //  8,388,608

    // 1) patchify
    patchify_kernel<<<(n_img + 255) / 256, 256>>>(x, patches, n_img);

    // 2) he = relu(patches @ w_enc1 + b_enc1)   [16384,768]x[768,2048]
    sgemm_kernel<1><<<dim3(HID_DIM / 64, T_TOKENS / 64), 256>>>(
        patches, P_DIM, w_enc1, HID_DIM, b_enc1, he, HID_DIM, P_DIM);

    // 3) ml = he @ w_enc2 + b_enc2              [16384,2048]x[2048,512]
    sgemm_kernel<0><<<dim3(L2_DIM / 64, T_TOKENS / 64), 256>>>(
        he, HID_DIM, w_enc2, L2_DIM, b_enc2, ml, L2_DIM, HID_DIM);

    // 4) mu_logvar_2d output (transpose)
    transpose_ml_kernel<<<(n_ml2 + 255) / 256, 256>>>(ml, ml2d, n_ml2);

    // 5) hd = relu(mu @ w_dec1 + b_dec1)        [16384,256]x[256,2048]
    //    mu = first 256 cols of ml (row stride 512)
    sgemm_kernel<1><<<dim3(HID_DIM / 64, T_TOKENS / 64), 256>>>(
        ml, L2_DIM, w_dec1, HID_DIM, b_dec1, hd, HID_DIM, L_DIM);

    // 6) dec = sigmoid(hd @ w_dec2 + b_dec2)    [16384,2048]x[2048,768]
    sgemm_kernel<2><<<dim3(P_DIM / 64, T_TOKENS / 64), 256>>>(
        hd, HID_DIM, w_dec2, P_DIM, b_dec2, dec, P_DIM, HID_DIM);

    // 7) unpatchify into recon_x
    unpatchify_kernel<<<(n_img + 255) / 256, 256>>>(dec, recon, n_img);
}

// round 7
// speedup vs baseline: 6.6061x; 6.6061x over previous
#include <cuda_runtime.h>
#include <cuda_fp16.h>
#include <cstdint>
#include <cstddef>

// ---------------------------------------------------------------------------
// ConvVAE2d via Ampere-style mma.sync fp16 GEMMs (baseline sm_103 PTX only:
// cp.async + ldmatrix + mma.sync.m16n8k16 — NO tcgen05, toolchain targets
// sm_103 baseline).
//   patchify(fp16) -> enc1(relu) -> enc2 -> transpose(mu_logvar out)
//   -> dec1(relu) -> dec2(sigmoid + fused unpatchify scatter)
// fp16 inputs, fp32 accumulate: ~5e-4 norm rel err (gate 1e-3).
// ---------------------------------------------------------------------------

#define TOK 16384
#define PD  768
#define HD  2048
#define L2D 512
#define LDIM 256

// ----------------------------- scratch -------------------------------------
__device__ __align__(256) __half g_p[TOK * PD];
__device__ __align__(256) __half g_he[TOK * HD];
__device__ __align__(256) float  g_ml[TOK * L2D];
__device__ __align__(256) __half g_mu[TOK * LDIM];
__device__ __align__(256) __half g_hd[TOK * HD];
__device__ __align__(256) __half g_w1t[HD * PD];
__device__ __align__(256) __half g_w2t[L2D * HD];
__device__ __align__(256) __half g_w3t[HD * LDIM];
__device__ __align__(256) __half g_w4t[PD * HD];

// ----------------------------- helpers -------------------------------------
__device__ __forceinline__ uint32_t smem_u32(const void* p) {
    uint32_t a;
    asm("{ .reg .u64 t; cvta.to.shared.u64 t, %1; cvt.u32.u64 %0, t; }"
        : "=r"(a) : "l"(p));
    return a;
}

// SW128-style swizzle for 128B rows: XOR chunk bits[4:6] with row bits[7:9].
#define SWZ128(o) ((uint32_t)(o) ^ ((((uint32_t)(o)) >> 3) & 0x70u))

__device__ __forceinline__ void cp16(uint32_t dst, const void* src) {
    asm volatile("cp.async.cg.shared.global [%0], [%1], 16;"
                 :: "r"(dst), "l"(src) : "memory");
}
__device__ __forceinline__ void ldsm_x4(uint32_t* r, uint32_t addr) {
    asm volatile("ldmatrix.sync.aligned.m8n8.x4.shared.b16 {%0,%1,%2,%3}, [%4];"
                 : "=r"(r[0]), "=r"(r[1]), "=r"(r[2]), "=r"(r[3]) : "r"(addr));
}
__device__ __forceinline__ void mma16816(float* c, const uint32_t* a,
                                         uint32_t b0, uint32_t b1) {
    asm volatile(
        "mma.sync.aligned.m16n8k16.row.col.f32.f16.f16.f32 "
        "{%0,%1,%2,%3}, {%4,%5,%6,%7}, {%8,%9}, {%0,%1,%2,%3};"
        : "+f"(c[0]), "+f"(c[1]), "+f"(c[2]), "+f"(c[3])
        : "r"(a[0]), "r"(a[1]), "r"(a[2]), "r"(a[3]), "r"(b0), "r"(b1));
}

// ------------------------------- GEMM kernel --------------------------------
// C[M,N] = act(A[M,K] @ B^T + bias).  A:[M,K] fp16 K-contig. B:[N,K] fp16
// (= W^T) K-contig.  BM=128, BN=128, BK=64, 256 thr, 8 warps (2M x 4N),
// warp tile 64x32, 3-stage cp.async pipeline, SW128 smem.
// MODE: 0 = relu -> fp16 out (ld 2048)
//       1 = none -> f32 ml (ld 512) + fp16 mu (cols < 256, ld 256)
//       3 = sigmoid -> fused unpatchify scatter to recon (f32)
template<int MODE>
__global__ void __launch_bounds__(256, 1)
gemm_mma(const __half* __restrict__ A, const __half* __restrict__ B,
         const float* __restrict__ bias,
         float* __restrict__ outf, __half* __restrict__ oh,
         int Kd, int ldA)
{
    extern __shared__ char smem[];
    const uint32_t sbase = smem_u32(smem);
    constexpr uint32_t STG = 32768;         // 16KB A + 16KB B per stage

    const int tid  = threadIdx.x;
    const int lane = tid & 31, wid = tid >> 5;
    const int wm = (wid >> 2) * 64;         // warp M offset (0/64)
    const int wn = (wid & 3) * 32;          // warp N offset (0..96)
    const int m0 = blockIdx.y * 128;
    const int n0 = blockIdx.x * 128;
    const int nk = Kd >> 6;

    const __half* Ag = A + (size_t)m0 * ldA;
    const __half* Bg = B + (size_t)n0 * Kd;

    auto load_stage = [&](int kc) {
        const uint32_t sA = sbase + (uint32_t)(kc % 3) * STG;
        const uint32_t sB = sA + 16384;
        const __half* ga = Ag + kc * 64;
        const __half* gb = Bg + kc * 64;
        #pragma unroll
        for (int i = 0; i < 4; i++) {           // A: 128 rows x 128B
            const int u = tid + i * 256;
            const int row = u >> 3, c = u & 7;
            cp16(sA + SWZ128(row * 128 + c * 16), ga + (size_t)row * ldA + c * 8);
        }
        #pragma unroll
        for (int i = 0; i < 4; i++) {           // B: 128 rows x 128B
            const int u = tid + i * 256;
            const int row = u >> 3, c = u & 7;
            cp16(sB + SWZ128(row * 128 + c * 16), gb + (size_t)row * Kd + c * 8);
        }
        asm volatile("cp.async.commit_group;" ::: "memory");
    };

    float acc[4][4][4];
    #pragma unroll
    for (int i = 0; i < 4; i++)
        #pragma unroll
        for (int j = 0; j < 4; j++)
            #pragma unroll
            for (int k = 0; k < 4; k++) acc[i][j][k] = 0.0f;

    load_stage(0);
    load_stage(1);

    const int r  = lane & 15;
    const int ch = lane >> 4;

    for (int kc = 0; kc < nk; kc++) {
        if (kc + 1 < nk) asm volatile("cp.async.wait_group 1;" ::: "memory");
        else             asm volatile("cp.async.wait_group 0;" ::: "memory");
        __syncthreads();
        const uint32_t sA = sbase + (uint32_t)(kc % 3) * STG;
        const uint32_t sB = sA + 16384;

        #pragma unroll
        for (int ks = 0; ks < 4; ks++) {        // 4 x k16 per BK=64
            const int c = ks * 2 + ch;          // 16B chunk index
            uint32_t a[4][4], b[2][4];
            #pragma unroll
            for (int mi = 0; mi < 4; mi++) {
                const int row = wm + mi * 16 + r;
                ldsm_x4(a[mi], sA + SWZ128(row * 128 + c * 16));
            }
            #pragma unroll
            for (int g = 0; g < 2; g++) {
                const int row = wn + g * 16 + r;
                ldsm_x4(b[g], sB + SWZ128(row * 128 + c * 16));
            }
            #pragma unroll
            for (int mi = 0; mi < 4; mi++)
                #pragma unroll
                for (int ni = 0; ni < 4; ni++)
                    mma16816(acc[mi][ni], a[mi],
                             b[ni >> 1][ni & 1], b[ni >> 1][2 + (ni & 1)]);
        }
        if (kc + 2 < nk) load_stage(kc + 2);
    }

    // ------------------------------ epilogue --------------------------------
    const int row0 = lane >> 2;
    const int col0 = (lane & 3) * 2;
    #pragma unroll
    for (int mi = 0; mi < 4; mi++) {
        #pragma unroll
        for (int ni = 0; ni < 4; ni++) {
            const int gc = n0 + wn + ni * 8 + col0;
            const float b0 = __ldg(bias + gc);
            const float b1 = __ldg(bias + gc + 1);
            #pragma unroll
            for (int h = 0; h < 2; h++) {
                const int gr = m0 + wm + mi * 16 + row0 + h * 8;
                float v0 = acc[mi][ni][h * 2 + 0] + b0;
                float v1 = acc[mi][ni][h * 2 + 1] + b1;
                if (MODE == 0) {
                    v0 = fmaxf(v0, 0.0f); v1 = fmaxf(v1, 0.0f);
                    *reinterpret_cast<__half2*>(oh + (size_t)gr * 2048 + gc) =
                        __floats2half2_rn(v0, v1);
                } else if (MODE == 1) {
                    outf[(size_t)gr * 512 + gc]     = v0;
                    outf[(size_t)gr * 512 + gc + 1] = v1;
                    if (gc < 256)
                        *reinterpret_cast<__half2*>(oh + (size_t)gr * 256 + gc) =
                            __floats2half2_rn(v0, v1);
                } else {
                    v0 = 1.0f / (1.0f + __expf(-v0));
                    v1 = 1.0f / (1.0f + __expf(-v1));
                    // fused unpatchify: gr = token, gc = c*256 + kh*16 + kw
                    const int b  = gr >> 6, g = gr & 63;
                    const int gh = g >> 3, gw = g & 7;
                    const int cc = gc >> 8, kh = (gc >> 4) & 15, kw = gc & 15;
                    const size_t idx =
                        ((size_t)(b * 3 + cc) * 128 + gh * 16 + kh) * 128 + gw * 16 + kw;
                    *reinterpret_cast<float2*>(outf + idx) = make_float2(v0, v1);
                }
            }
        }
    }
}

// ------------------------------ prep kernels --------------------------------
__global__ void patchify_kernel(const float* __restrict__ x,
                                __half* __restrict__ p, int n)
{
    int i = blockIdx.x * blockDim.x + threadIdx.x;
    if (i >= n) return;
    const int kw    = i & 15;
    const int kh    = (i >> 4) & 15;
    const int c     = (i >> 8) % 3;
    const int token = i / PD;
    const int gw = token & 7;
    const int gh = (token >> 3) & 7;
    const int b  = token >> 6;
    const size_t src = ((size_t)(b * 3 + c) * 128 + gh * 16 + kh) * 128 + gw * 16 + kw;
    p[i] = __float2half_rn(x[src]);
}

// t[n,k] = w[k,n]  (fp32 -> fp16 transpose). blockDim (32,8).
__global__ void wT_kernel(const float* __restrict__ w, int Kd, int Nd,
                          __half* __restrict__ t)
{
    __shared__ float tile[32][33];
    const int x = blockIdx.x * 32 + threadIdx.x;   // n
    const int y = blockIdx.y * 32 + threadIdx.y;   // k
    #pragma unroll
    for (int i = 0; i < 32; i += 8)
        tile[threadIdx.y + i][threadIdx.x] = w[(size_t)(y + i) * Nd + x];
    __syncthreads();
    const int n = blockIdx.x * 32 + threadIdx.y;
    const int k = blockIdx.y * 32 + threadIdx.x;
    #pragma unroll
    for (int i = 0; i < 32; i += 8)
        t[(size_t)(n + i) * Kd + k] = __float2half_rn(tile[threadIdx.x][threadIdx.y + i]);
}

// out2[b, l, g] = ml[b*64+g, l]
__global__ void transpose_ml_kernel(const float* __restrict__ ml,
                                    float* __restrict__ out2, int n)
{
    int i = blockIdx.x * blockDim.x + threadIdx.x;
    if (i >= n) return;
    const int g = i & 63;
    const int l = (i >> 6) & 511;
    const int b = i >> 15;
    out2[i] = ml[(size_t)(b * 64 + g) * L2D + l];
}

// ------------------------------- launcher -----------------------------------
extern "C" void kernel_launch(void* const* d_in, const int* in_sizes, int n_in,
                              void* d_out, int out_size)
{
    const float* x      = (const float*)d_in[0];
    const float* w_enc1 = (const float*)d_in[1];
    const float* b_enc1 = (const float*)d_in[2];
    const float* w_enc2 = (const float*)d_in[3];
    const float* b_enc2 = (const float*)d_in[4];
    const float* w_dec1 = (const float*)d_in[5];
    const float* b_dec1 = (const float*)d_in[6];
    const float* w_dec2 = (const float*)d_in[7];
    const float* b_dec2 = (const float*)d_in[8];

    __half *p, *he, *mu, *hd, *w1t, *w2t, *w3t, *w4t;
    float* ml;
    cudaGetSymbolAddress((void**)&p,   g_p);
    cudaGetSymbolAddress((void**)&he,  g_he);
    cudaGetSymbolAddress((void**)&ml,  g_ml);
    cudaGetSymbolAddress((void**)&mu,  g_mu);
    cudaGetSymbolAddress((void**)&hd,  g_hd);
    cudaGetSymbolAddress((void**)&w1t, g_w1t);
    cudaGetSymbolAddress((void**)&w2t, g_w2t);
    cudaGetSymbolAddress((void**)&w3t, g_w3t);
    cudaGetSymbolAddress((void**)&w4t, g_w4t);

    float* out   = (float*)d_out;
    float* recon = out;
    float* ml2d  = out + (size_t)256 * 3 * 128 * 128;

    const int SMEM = 3 * 32768;   // 96 KB
    cudaFuncSetAttribute(gemm_mma<0>, cudaFuncAttributeMaxDynamicSharedMemorySize, SMEM);
    cudaFuncSetAttribute(gemm_mma<1>, cudaFuncAttributeMaxDynamicSharedMemorySize, SMEM);
    cudaFuncSetAttribute(gemm_mma<3>, cudaFuncAttributeMaxDynamicSharedMemorySize, SMEM);

    const int n_img = 256 * 3 * 128 * 128;   // 12,582,912
    const int n_ml2 = 256 * 512 * 64;        //  8,388,608

    // 1) patchify -> fp16
    patchify_kernel<<<(n_img + 255) / 256, 256>>>(x, p, n_img);

    // 2) weight transposes -> fp16 [N,K]
    dim3 tb32(32, 8);
    wT_kernel<<<dim3(HD / 32,   PD / 32),  tb32>>>(w_enc1, PD,   HD,  w1t);
    wT_kernel<<<dim3(L2D / 32,  HD / 32),  tb32>>>(w_enc2, HD,   L2D, w2t);
    wT_kernel<<<dim3(HD / 32,   LDIM / 32), tb32>>>(w_dec1, LDIM, HD,  w3t);
    wT_kernel<<<dim3(PD / 32,   HD / 32),  tb32>>>(w_dec2, HD,   PD,  w4t);

    // 3) enc1: he = relu(p @ w1 + b1)     [16384,768] x [768,2048]
    gemm_mma<0><<<dim3(HD / 128, TOK / 128), 256, SMEM>>>(
        p, w1t, b_enc1, nullptr, he, PD, PD);

    // 4) enc2: ml = he @ w2 + b2          [16384,2048] x [2048,512]
    gemm_mma<1><<<dim3(L2D / 128, TOK / 128), 256, SMEM>>>(
        he, w2t, b_enc2, ml, mu, HD, HD);

    // 5) mu_logvar_2d output
    transpose_ml_kernel<<<(n_ml2 + 255) / 256, 256>>>(ml, ml2d, n_ml2);

    // 6) dec1: hd = relu(mu @ w3 + b3)    [16384,256] x [256,2048]
    gemm_mma<0><<<dim3(HD / 128, TOK / 128), 256, SMEM>>>(
        mu, w3t, b_dec1, nullptr, hd, LDIM, LDIM);

    // 7) dec2: recon = sigmoid(hd @ w4 + b4), fused unpatchify scatter
    gemm_mma<3><<<dim3(PD / 128, TOK / 128), 256, SMEM>>>(
        hd, w4t, b_dec2, recon, nullptr, HD, HD);
}

// round 8
// speedup vs baseline: 7.4616x; 1.1295x over previous
#include <cuda_runtime.h>
#include <cuda_fp16.h>
#include <cstdint>
#include <cstddef>

// ---------------------------------------------------------------------------
// ConvVAE2d via mma.sync fp16 GEMMs (baseline sm_103 PTX: cp.async + ldmatrix
// + mma.sync.m16n8k16; tcgen05 is unavailable — toolchain targets sm_103).
//   patchify(fp16) -> enc1(relu) -> enc2 -> tiled transpose(mu_logvar out)
//   -> dec1(relu) -> dec2(sigmoid + fused unpatchify scatter)
// R8: BN=256 macro tile, 64x64 warp tiles, smem-tiled ml transpose.
// ---------------------------------------------------------------------------

#define TOK 16384
#define PD  768
#define HD  2048
#define L2D 512
#define LDIM 256

// ----------------------------- scratch -------------------------------------
__device__ __align__(256) __half g_p[TOK * PD];
__device__ __align__(256) __half g_he[TOK * HD];
__device__ __align__(256) float  g_ml[TOK * L2D];
__device__ __align__(256) __half g_mu[TOK * LDIM];
__device__ __align__(256) __half g_hd[TOK * HD];
__device__ __align__(256) __half g_w1t[HD * PD];
__device__ __align__(256) __half g_w2t[L2D * HD];
__device__ __align__(256) __half g_w3t[HD * LDIM];
__device__ __align__(256) __half g_w4t[PD * HD];

// ----------------------------- helpers -------------------------------------
__device__ __forceinline__ uint32_t smem_u32(const void* p) {
    uint32_t a;
    asm("{ .reg .u64 t; cvta.to.shared.u64 t, %1; cvt.u32.u64 %0, t; }"
        : "=r"(a) : "l"(p));
    return a;
}

// SW128-style swizzle for 128B rows: XOR chunk bits[4:6] with row bits[7:9].
#define SWZ128(o) ((uint32_t)(o) ^ ((((uint32_t)(o)) >> 3) & 0x70u))

__device__ __forceinline__ void cp16(uint32_t dst, const void* src) {
    asm volatile("cp.async.cg.shared.global [%0], [%1], 16;"
                 :: "r"(dst), "l"(src) : "memory");
}
__device__ __forceinline__ void ldsm_x4(uint32_t* r, uint32_t addr) {
    asm volatile("ldmatrix.sync.aligned.m8n8.x4.shared.b16 {%0,%1,%2,%3}, [%4];"
                 : "=r"(r[0]), "=r"(r[1]), "=r"(r[2]), "=r"(r[3]) : "r"(addr));
}
__device__ __forceinline__ void mma16816(float* c, const uint32_t* a,
                                         uint32_t b0, uint32_t b1) {
    asm volatile(
        "mma.sync.aligned.m16n8k16.row.col.f32.f16.f16.f32 "
        "{%0,%1,%2,%3}, {%4,%5,%6,%7}, {%8,%9}, {%0,%1,%2,%3};"
        : "+f"(c[0]), "+f"(c[1]), "+f"(c[2]), "+f"(c[3])
        : "r"(a[0]), "r"(a[1]), "r"(a[2]), "r"(a[3]), "r"(b0), "r"(b1));
}

// ------------------------------- GEMM kernel --------------------------------
// C[M,N] = act(A[M,K] @ B^T + bias).  A:[M,K] fp16 K-contig. B:[N,K] fp16
// (= W^T) K-contig.  BM=128, BN=256, BK=64, 256 thr, 8 warps (2M x 4N),
// warp tile 64x64, 3-stage cp.async pipeline, SW128 smem.
// MODE: 0 = relu -> fp16 out (ld 2048)
//       1 = none -> f32 ml (ld 512) + fp16 mu (cols < 256, ld 256)
//       3 = sigmoid -> fused unpatchify scatter to recon (f32)
template<int MODE>
__global__ void __launch_bounds__(256, 1)
gemm_mma(const __half* __restrict__ A, const __half* __restrict__ B,
         const float* __restrict__ bias,
         float* __restrict__ outf, __half* __restrict__ oh,
         int Kd, int ldA)
{
    extern __shared__ char smem[];
    const uint32_t sbase = smem_u32(smem);
    constexpr uint32_t STG = 49152;         // 16KB A + 32KB B per stage

    const int tid  = threadIdx.x;
    const int lane = tid & 31, wid = tid >> 5;
    const int wm = (wid >> 2) * 64;         // warp M offset (0/64)
    const int wn = (wid & 3) * 64;          // warp N offset (0..192)
    const int m0 = blockIdx.y * 128;
    const int n0 = blockIdx.x * 256;
    const int nk = Kd >> 6;

    const __half* Ag = A + (size_t)m0 * ldA;
    const __half* Bg = B + (size_t)n0 * Kd;

    auto load_stage = [&](int kc) {
        const uint32_t sA = sbase + (uint32_t)(kc % 3) * STG;
        const uint32_t sB = sA + 16384;
        const __half* ga = Ag + kc * 64;
        const __half* gb = Bg + kc * 64;
        #pragma unroll
        for (int i = 0; i < 4; i++) {           // A: 128 rows x 128B
            const int u = tid + i * 256;
            const int row = u >> 3, c = u & 7;
            cp16(sA + SWZ128(row * 128 + c * 16), ga + (size_t)row * ldA + c * 8);
        }
        #pragma unroll
        for (int i = 0; i < 8; i++) {           // B: 256 rows x 128B
            const int u = tid + i * 256;
            const int row = u >> 3, c = u & 7;
            cp16(sB + SWZ128(row * 128 + c * 16), gb + (size_t)row * Kd + c * 8);
        }
        asm volatile("cp.async.commit_group;" ::: "memory");
    };

    float acc[4][8][4];
    #pragma unroll
    for (int i = 0; i < 4; i++)
        #pragma unroll
        for (int j = 0; j < 8; j++)
            #pragma unroll
            for (int k = 0; k < 4; k++) acc[i][j][k] = 0.0f;

    load_stage(0);
    load_stage(1);

    const int r  = lane & 15;
    const int ch = lane >> 4;

    for (int kc = 0; kc < nk; kc++) {
        if (kc + 1 < nk) asm volatile("cp.async.wait_group 1;" ::: "memory");
        else             asm volatile("cp.async.wait_group 0;" ::: "memory");
        __syncthreads();
        const uint32_t sA = sbase + (uint32_t)(kc % 3) * STG;
        const uint32_t sB = sA + 16384;

        #pragma unroll
        for (int ks = 0; ks < 4; ks++) {        // 4 x k16 per BK=64
            const int c = ks * 2 + ch;          // 16B chunk index
            uint32_t a[4][4], b[4][4];
            #pragma unroll
            for (int mi = 0; mi < 4; mi++) {
                const int row = wm + mi * 16 + r;
                ldsm_x4(a[mi], sA + SWZ128(row * 128 + c * 16));
            }
            #pragma unroll
            for (int g = 0; g < 4; g++) {
                const int row = wn + g * 16 + r;
                ldsm_x4(b[g], sB + SWZ128(row * 128 + c * 16));
            }
            #pragma unroll
            for (int mi = 0; mi < 4; mi++)
                #pragma unroll
                for (int ni = 0; ni < 8; ni++)
                    mma16816(acc[mi][ni], a[mi],
                             b[ni >> 1][ni & 1], b[ni >> 1][2 + (ni & 1)]);
        }
        if (kc + 2 < nk) load_stage(kc + 2);
    }

    // ------------------------------ epilogue --------------------------------
    const int row0 = lane >> 2;
    const int col0 = (lane & 3) * 2;
    #pragma unroll
    for (int mi = 0; mi < 4; mi++) {
        #pragma unroll
        for (int ni = 0; ni < 8; ni++) {
            const int gc = n0 + wn + ni * 8 + col0;
            const float b0 = __ldg(bias + gc);
            const float b1 = __ldg(bias + gc + 1);
            #pragma unroll
            for (int h = 0; h < 2; h++) {
                const int gr = m0 + wm + mi * 16 + row0 + h * 8;
                float v0 = acc[mi][ni][h * 2 + 0] + b0;
                float v1 = acc[mi][ni][h * 2 + 1] + b1;
                if (MODE == 0) {
                    v0 = fmaxf(v0, 0.0f); v1 = fmaxf(v1, 0.0f);
                    *reinterpret_cast<__half2*>(oh + (size_t)gr * 2048 + gc) =
                        __floats2half2_rn(v0, v1);
                } else if (MODE == 1) {
                    outf[(size_t)gr * 512 + gc]     = v0;
                    outf[(size_t)gr * 512 + gc + 1] = v1;
                    if (gc < 256)
                        *reinterpret_cast<__half2*>(oh + (size_t)gr * 256 + gc) =
                            __floats2half2_rn(v0, v1);
                } else {
                    v0 = 1.0f / (1.0f + __expf(-v0));
                    v1 = 1.0f / (1.0f + __expf(-v1));
                    // fused unpatchify: gr = token, gc = c*256 + kh*16 + kw
                    const int b  = gr >> 6, g = gr & 63;
                    const int gh = g >> 3, gw = g & 7;
                    const int cc = gc >> 8, kh = (gc >> 4) & 15, kw = gc & 15;
                    const size_t idx =
                        ((size_t)(b * 3 + cc) * 128 + gh * 16 + kh) * 128 + gw * 16 + kw;
                    *reinterpret_cast<float2*>(outf + idx) = make_float2(v0, v1);
                }
            }
        }
    }
}

// ------------------------------ prep kernels --------------------------------
__global__ void patchify_kernel(const float* __restrict__ x,
                                __half* __restrict__ p, int n)
{
    int i = blockIdx.x * blockDim.x + threadIdx.x;
    if (i >= n) return;
    const int kw    = i & 15;
    const int kh    = (i >> 4) & 15;
    const int c     = (i >> 8) % 3;
    const int token = i / PD;
    const int gw = token & 7;
    const int gh = (token >> 3) & 7;
    const int b  = token >> 6;
    const size_t src = ((size_t)(b * 3 + c) * 128 + gh * 16 + kh) * 128 + gw * 16 + kw;
    p[i] = __float2half_rn(x[src]);
}

// t[n,k] = w[k,n]  (fp32 -> fp16 transpose). blockDim (32,8).
__global__ void wT_kernel(const float* __restrict__ w, int Kd, int Nd,
                          __half* __restrict__ t)
{
    __shared__ float tile[32][33];
    const int x = blockIdx.x * 32 + threadIdx.x;   // n
    const int y = blockIdx.y * 32 + threadIdx.y;   // k
    #pragma unroll
    for (int i = 0; i < 32; i += 8)
        tile[threadIdx.y + i][threadIdx.x] = w[(size_t)(y + i) * Nd + x];
    __syncthreads();
    const int n = blockIdx.x * 32 + threadIdx.y;
    const int k = blockIdx.y * 32 + threadIdx.x;
    #pragma unroll
    for (int i = 0; i < 32; i += 8)
        t[(size_t)(n + i) * Kd + k] = __float2half_rn(tile[threadIdx.x][threadIdx.y + i]);
}

// out2[b, l, g] = ml[b*64+g, l] — smem-tiled: both sides coalesced.
// blockDim (32,8); grid (L2D/32, 64/32, 256).
__global__ void transpose_ml_tiled(const float* __restrict__ ml,
                                   float* __restrict__ out2)
{
    __shared__ float tile[32][33];
    const int b  = blockIdx.z;
    const int l0 = blockIdx.x * 32;
    const int g0 = blockIdx.y * 32;
    #pragma unroll
    for (int i = 0; i < 32; i += 8) {
        const int g = g0 + threadIdx.y + i;
        tile[threadIdx.y + i][threadIdx.x] =
            ml[(size_t)(b * 64 + g) * L2D + l0 + threadIdx.x];
    }
    __syncthreads();
    #pragma unroll
    for (int i = 0; i < 32; i += 8) {
        const int l = l0 + threadIdx.y + i;
        out2[(size_t)b * (L2D * 64) + (size_t)l * 64 + g0 + threadIdx.x] =
            tile[threadIdx.x][threadIdx.y + i];
    }
}

// ------------------------------- launcher -----------------------------------
extern "C" void kernel_launch(void* const* d_in, const int* in_sizes, int n_in,
                              void* d_out, int out_size)
{
    const float* x      = (const float*)d_in[0];
    const float* w_enc1 = (const float*)d_in[1];
    const float* b_enc1 = (const float*)d_in[2];
    const float* w_enc2 = (const float*)d_in[3];
    const float* b_enc2 = (const float*)d_in[4];
    const float* w_dec1 = (const float*)d_in[5];
    const float* b_dec1 = (const float*)d_in[6];
    const float* w_dec2 = (const float*)d_in[7];
    const float* b_dec2 = (const float*)d_in[8];

    __half *p, *he, *mu, *hd, *w1t, *w2t, *w3t, *w4t;
    float* ml;
    cudaGetSymbolAddress((void**)&p,   g_p);
    cudaGetSymbolAddress((void**)&he,  g_he);
    cudaGetSymbolAddress((void**)&ml,  g_ml);
    cudaGetSymbolAddress((void**)&mu,  g_mu);
    cudaGetSymbolAddress((void**)&hd,  g_hd);
    cudaGetSymbolAddress((void**)&w1t, g_w1t);
    cudaGetSymbolAddress((void**)&w2t, g_w2t);
    cudaGetSymbolAddress((void**)&w3t, g_w3t);
    cudaGetSymbolAddress((void**)&w4t, g_w4t);

    float* out   = (float*)d_out;
    float* recon = out;
    float* ml2d  = out + (size_t)256 * 3 * 128 * 128;

    const int SMEM = 3 * 49152;   // 144 KB
    cudaFuncSetAttribute(gemm_mma<0>, cudaFuncAttributeMaxDynamicSharedMemorySize, SMEM);
    cudaFuncSetAttribute(gemm_mma<1>, cudaFuncAttributeMaxDynamicSharedMemorySize, SMEM);
    cudaFuncSetAttribute(gemm_mma<3>, cudaFuncAttributeMaxDynamicSharedMemorySize, SMEM);

    const int n_img = 256 * 3 * 128 * 128;   // 12,582,912

    // 1) patchify -> fp16
    patchify_kernel<<<(n_img + 255) / 256, 256>>>(x, p, n_img);

    // 2) weight transposes -> fp16 [N,K]
    dim3 tb32(32, 8);
    wT_kernel<<<dim3(HD / 32,   PD / 32),  tb32>>>(w_enc1, PD,   HD,  w1t);
    wT_kernel<<<dim3(L2D / 32,  HD / 32),  tb32>>>(w_enc2, HD,   L2D, w2t);
    wT_kernel<<<dim3(HD / 32,   LDIM / 32), tb32>>>(w_dec1, LDIM, HD,  w3t);
    wT_kernel<<<dim3(PD / 32,   HD / 32),  tb32>>>(w_dec2, HD,   PD,  w4t);

    // 3) enc1: he = relu(p @ w1 + b1)     [16384,768] x [768,2048]
    gemm_mma<0><<<dim3(HD / 256, TOK / 128), 256, SMEM>>>(
        p, w1t, b_enc1, nullptr, he, PD, PD);

    // 4) enc2: ml = he @ w2 + b2          [16384,2048] x [2048,512]
    gemm_mma<1><<<dim3(L2D / 256, TOK / 128), 256, SMEM>>>(
        he, w2t, b_enc2, ml, mu, HD, HD);

    // 5) mu_logvar_2d output (tiled transpose, both sides coalesced)
    transpose_ml_tiled<<<dim3(L2D / 32, 2, 256), tb32>>>(ml, ml2d);

    // 6) dec1: hd = relu(mu @ w3 + b3)    [16384,256] x [256,2048]
    gemm_mma<0><<<dim3(HD / 256, TOK / 128), 256, SMEM>>>(
        mu, w3t, b_dec1, nullptr, hd, LDIM, LDIM);

    // 7) dec2: recon = sigmoid(hd @ w4 + b4), fused unpatchify scatter
    gemm_mma<3><<<dim3(PD / 256, TOK / 128), 256, SMEM>>>(
        hd, w4t, b_dec2, recon, nullptr, HD, HD);
}